// round 10
// baseline (speedup 1.0000x reference)
#include <cuda_runtime.h>
#include <math.h>
#include <stdint.h>

#define BATCH 8192
#define NCLS  10
#define FEAT  64
#define HID   128
#define KTOT  (NCLS * HID)   // 1280
#define MTOT  (NCLS * BATCH) // 81920 rows, row = n*8192 + b

// ---------------------------------------------------------------------------
// Static scratch, ~43.8 MB total.
// g_buf phases:
//   [0, 10485760)            phase 1-2: UV f32 (u+b1 cols 0-63, v cols 64-127)
//                            phase 3-5: Y  tf32 bits (row = i*8192+b)
//   [10485760, 11304960)     phase 2-3: adj f32 [8192][100]
// ---------------------------------------------------------------------------
#define UV_OFF  0
#define ADJ_OFF 10485760
__device__ __align__(16) float    g_buf[11304960];
__device__ __align__(16) uint32_t g_E[NCLS * HID * HID];   // tf32 E[i][k][h]
__device__ __align__(16) float    g_c0p[NCLS * HID];       // f32 partial c0

__device__ __forceinline__ uint32_t f2tf32(float x) {
    uint32_t r;
    asm("cvt.rna.tf32.f32 %0, %1;" : "=r"(r) : "f"(x));
    return r;
}

#define MMA_TF32(C, A0, A1, A2, A3, B0, B1)                                  \
    asm volatile(                                                            \
        "mma.sync.aligned.m16n8k8.row.col.f32.tf32.tf32.f32 "               \
        "{%0,%1,%2,%3}, {%4,%5,%6,%7}, {%8,%9}, {%0,%1,%2,%3};"             \
        : "+f"((C)[0]), "+f"((C)[1]), "+f"((C)[2]), "+f"((C)[3])            \
        : "r"(A0), "r"(A1), "r"(A2), "r"(A3), "r"(B0), "r"(B1))

#define GA_STR 68    // 68 mod 32 = 4 -> A-frag banks 4g+tg distinct
#define GB_STR 136   // 136 mod 32 = 8 -> B-frag banks 8tg+g distinct

// ---------------------------------------------------------------------------
// Kernel 1: UV = nd @ [W1u | W1v] (+b1 on u cols). M=81920, N=128, K=64.
// grid 640, 256 threads, block tile 128x128, warp tile 64x32.
// ---------------------------------------------------------------------------
__global__ void __launch_bounds__(256) uv_gemm(
    const float* __restrict__ A, const float* __restrict__ W1,
    const float* __restrict__ b1)
{
    extern __shared__ uint32_t gs[];
    uint32_t* sA = gs;                 // [128][GA_STR]
    uint32_t* sB = gs + 128 * GA_STR;  // [64][GB_STR]
    float* sbias = (float*)(sB + 64 * GB_STR);

    const int t  = threadIdx.x;
    const int m0 = blockIdx.x * 128;

    {
        const float4* ap = (const float4*)(A + (size_t)m0 * 64);
        for (int idx = t; idx < 2048; idx += 256) {
            float4 v = ap[idx];
            int row = idx >> 4, c4 = (idx & 15) * 4;
            uint32_t* d = &sA[row * GA_STR + c4];
            d[0] = f2tf32(v.x); d[1] = f2tf32(v.y);
            d[2] = f2tf32(v.z); d[3] = f2tf32(v.w);
        }
    }
    for (int idx = t; idx < 8192; idx += 256) {
        int k = idx >> 7, c = idx & 127;
        float f = (c < 64) ? W1[k * 64 + c] : W1[(64 + k) * 64 + (c - 64)];
        sB[k * GB_STR + c] = f2tf32(f);
    }
    if (t < 64) sbias[t] = b1[t];
    __syncthreads();

    const int wid  = t >> 5;
    const int lane = t & 31;
    const int g    = lane >> 2;
    const int tg   = lane & 3;
    const int wm   = wid >> 2;
    const int wn   = wid & 3;

    float c[4][4][4];
#pragma unroll
    for (int mf = 0; mf < 4; mf++)
#pragma unroll
        for (int nf = 0; nf < 4; nf++)
#pragma unroll
            for (int q = 0; q < 4; q++) c[mf][nf][q] = 0.f;

#pragma unroll
    for (int kk = 0; kk < 8; kk++) {
        uint32_t a[4][4], bf[4][2];
#pragma unroll
        for (int mf = 0; mf < 4; mf++) {
            const uint32_t* ap = &sA[(wm * 64 + mf * 16 + g) * GA_STR + kk * 8 + tg];
            a[mf][0] = ap[0];
            a[mf][1] = ap[8 * GA_STR];
            a[mf][2] = ap[4];
            a[mf][3] = ap[8 * GA_STR + 4];
        }
#pragma unroll
        for (int nf = 0; nf < 4; nf++) {
            const uint32_t* bp = &sB[(kk * 8 + tg) * GB_STR + wn * 32 + nf * 8 + g];
            bf[nf][0] = bp[0];
            bf[nf][1] = bp[4 * GB_STR];
        }
#pragma unroll
        for (int mf = 0; mf < 4; mf++)
#pragma unroll
            for (int nf = 0; nf < 4; nf++)
                MMA_TF32(c[mf][nf], a[mf][0], a[mf][1], a[mf][2], a[mf][3],
                         bf[nf][0], bf[nf][1]);
    }

    float* UV = g_buf + UV_OFF;
#pragma unroll
    for (int mf = 0; mf < 4; mf++) {
#pragma unroll
        for (int nf = 0; nf < 4; nf++) {
            const int row = m0 + wm * 64 + mf * 16 + g;
            const int col = wn * 32 + nf * 8 + 2 * tg;
            float b0 = (col < 64) ? sbias[col] : 0.f;
            float b1v = (col < 64) ? sbias[col + 1] : 0.f;
            *(float2*)&UV[(size_t)row * 128 + col] =
                make_float2(c[mf][nf][0] + b0, c[mf][nf][1] + b1v);
            *(float2*)&UV[(size_t)(row + 8) * 128 + col] =
                make_float2(c[mf][nf][2] + b0, c[mf][nf][3] + b1v);
        }
    }
}

// ---------------------------------------------------------------------------
// Kernel 2: adjacency only. One warp per batch, 8 warps/block, grid 1024.
// adj[b][i*10+j] = sigmoid(relu(u_i+v_j).W2 + b2), diag = 1.
// wb 16B-aligned (float4 stores land in it); sb2 padded to 4 words.
// ---------------------------------------------------------------------------
#define AJ_STR 68

__global__ void __launch_bounds__(256) adj_kernel(
    const float* __restrict__ W2, const float* __restrict__ b2)
{
    __shared__ __align__(16) float wb[8 * 2 * 10 * AJ_STR];  // su/sv per warp
    __shared__ __align__(16) float sW2[64];
    __shared__ float sb2[4];

    const int t = threadIdx.x;
    if (t < 64) sW2[t] = W2[t];
    if (t == 64) sb2[0] = b2[0];
    __syncthreads();

    const int wid  = t >> 5;
    const int lane = t & 31;
    const int b    = blockIdx.x * 8 + wid;

    float* su = wb + wid * (2 * 10 * AJ_STR);
    float* sv = su + 10 * AJ_STR;

    const float* UV = g_buf + UV_OFF;
    {
        const int c4 = 4 * lane;
#pragma unroll
        for (int n = 0; n < NCLS; n++) {
            float4 v = *(const float4*)&UV[((size_t)(n * BATCH + b)) * 128 + c4];
            if (c4 < 64) *(float4*)&su[n * AJ_STR + c4] = v;
            else         *(float4*)&sv[n * AJ_STR + c4 - 64] = v;
        }
    }
    __syncwarp();

    float* adj = g_buf + ADJ_OFF + (size_t)b * 100;
    const float b2v = sb2[0];
    for (int p = lane; p < 100; p += 32) {
        int i = p / 10, j = p - i * 10;
        float s = b2v;
#pragma unroll 4
        for (int q = 0; q < 16; q++) {
            float4 u4 = *(const float4*)&su[i * AJ_STR + 4 * q];
            float4 v4 = *(const float4*)&sv[j * AJ_STR + 4 * q];
            float4 w4 = *(const float4*)&sW2[4 * q];
            s = fmaf(fmaxf(u4.x + v4.x, 0.f), w4.x, s);
            s = fmaf(fmaxf(u4.y + v4.y, 0.f), w4.y, s);
            s = fmaf(fmaxf(u4.z + v4.z, 0.f), w4.z, s);
            s = fmaf(fmaxf(u4.w + v4.w, 0.f), w4.w, s);
        }
        adj[p] = (i == j) ? 1.0f : (1.0f / (1.0f + __expf(-s)));
    }
}

// ---------------------------------------------------------------------------
// Kernel 3: y_gemm. Block = 16 batches x 10 nodes = 160 rows. grid 512.
// Builds X = nd_i + sum_j adj[i][j] nd_j in smem (tf32), then
// Y = relu(X @ G1 + g1) -> tf32 into g_buf[0..] (UV dead).
// 8 warps: wm (2) x wn (4); warp tile 80x32 (5 m-frags).
// ---------------------------------------------------------------------------
#define ND_STR 66
#define ADJ_PAD 104

__global__ void __launch_bounds__(256) y_gemm(
    const float* __restrict__ hidden,
    const float* __restrict__ G1, const float* __restrict__ g1)
{
    extern __shared__ uint32_t ys[];
    uint32_t* sA  = ys;                          // [160][GA_STR] tf32 X
    uint32_t* sB  = ys + 160 * GA_STR;           // [64][GB_STR] tf32 G1
    float* snd    = (float*)(sB + 64 * GB_STR);  // [10*16][ND_STR]
    float* sadj   = snd + 160 * ND_STR;          // [16][ADJ_PAD]
    float* sbias  = sadj + 16 * ADJ_PAD;         // [128]

    const int t  = threadIdx.x;
    const int b0 = blockIdx.x * 16;

    // load nd: hidden[(n*8192 + b0+bl)*64 + f]
    for (int idx = t; idx < 10240; idx += 256) {
        int n = idx >> 10, rem = idx & 1023;
        int bl = rem >> 6, f = rem & 63;
        snd[(n * 16 + bl) * ND_STR + f] =
            hidden[((size_t)n * BATCH + b0 + bl) * 64 + f];
    }
    // load adj rows for 16 batches
    {
        const float* ap = g_buf + ADJ_OFF + (size_t)b0 * 100;
        for (int idx = t; idx < 1600; idx += 256) {
            int bl = idx / 100, p = idx - bl * 100;
            sadj[bl * ADJ_PAD + p] = ap[bl * 100 + p];
        }
    }
    // load B = G1 (tf32) and bias
    for (int idx = t; idx < 8192; idx += 256) {
        int k = idx >> 7, c = idx & 127;
        sB[k * GB_STR + c] = f2tf32(G1[idx]);
    }
    if (t < 128) sbias[t] = g1[t];
    __syncthreads();

    // build X into sA (tf32): X[r][f], r = i*16+bl
    for (int idx = t; idx < 10240; idx += 256) {
        int r = idx >> 6, f = idx & 63;
        int i = r >> 4, bl = r & 15;
        float x = snd[r * ND_STR + f];
        const float* arow = &sadj[bl * ADJ_PAD + i * 10];
#pragma unroll
        for (int j = 0; j < NCLS; j++)
            x = fmaf(arow[j], snd[(j * 16 + bl) * ND_STR + f], x);
        sA[r * GA_STR + f] = f2tf32(x);
    }
    __syncthreads();

    const int wid  = t >> 5;
    const int lane = t & 31;
    const int g    = lane >> 2;
    const int tg   = lane & 3;
    const int wm   = wid >> 2;    // 0..1 -> rows wm*80
    const int wn   = wid & 3;     // 0..3 -> cols wn*32

    float c[5][4][4];
#pragma unroll
    for (int mf = 0; mf < 5; mf++)
#pragma unroll
        for (int nf = 0; nf < 4; nf++)
#pragma unroll
            for (int q = 0; q < 4; q++) c[mf][nf][q] = 0.f;

#pragma unroll
    for (int kk = 0; kk < 8; kk++) {
        uint32_t a[5][4], bf[4][2];
#pragma unroll
        for (int mf = 0; mf < 5; mf++) {
            const uint32_t* ap = &sA[(wm * 80 + mf * 16 + g) * GA_STR + kk * 8 + tg];
            a[mf][0] = ap[0];
            a[mf][1] = ap[8 * GA_STR];
            a[mf][2] = ap[4];
            a[mf][3] = ap[8 * GA_STR + 4];
        }
#pragma unroll
        for (int nf = 0; nf < 4; nf++) {
            const uint32_t* bp = &sB[(kk * 8 + tg) * GB_STR + wn * 32 + nf * 8 + g];
            bf[nf][0] = bp[0];
            bf[nf][1] = bp[4 * GB_STR];
        }
#pragma unroll
        for (int mf = 0; mf < 5; mf++)
#pragma unroll
            for (int nf = 0; nf < 4; nf++)
                MMA_TF32(c[mf][nf], a[mf][0], a[mf][1], a[mf][2], a[mf][3],
                         bf[nf][0], bf[nf][1]);
    }

    uint32_t* Y = (uint32_t*)(g_buf + UV_OFF);
#pragma unroll
    for (int mf = 0; mf < 5; mf++) {
#pragma unroll
        for (int nf = 0; nf < 4; nf++) {
            const int col = wn * 32 + nf * 8 + 2 * tg;
            const float gg0 = sbias[col], gg1 = sbias[col + 1];
#pragma unroll
            for (int h = 0; h < 2; h++) {
                const int r = wm * 80 + mf * 16 + g + h * 8;
                const int i = r >> 4, bl = r & 15;
                const size_t grow = (size_t)i * BATCH + b0 + bl;
                uint2 o;
                o.x = f2tf32(fmaxf(c[mf][nf][0 + 2 * h] + gg0, 0.f));
                o.y = f2tf32(fmaxf(c[mf][nf][1 + 2 * h] + gg1, 0.f));
                *(uint2*)&Y[grow * 128 + col] = o;
            }
        }
    }
}

// ---------------------------------------------------------------------------
// prep: E = G2 @ D1_i (tf32) + c0 partials. grid 50 x 256.
// ---------------------------------------------------------------------------
__global__ void __launch_bounds__(256) prep_kernel(
    const float* __restrict__ G2, const float* __restrict__ g2,
    const float* __restrict__ D1)
{
    const int bx = blockIdx.x;
    const int t  = threadIdx.x;

    if (bx >= 40) {
        const int i = bx - 40;
        if (t < 128) {
            const float* dp = D1 + (size_t)(i * 128) * 128 + t;
            float s = 0.f;
            for (int r0 = 0; r0 < 128; r0 += 8) {
                float dv[8];
#pragma unroll
                for (int j = 0; j < 8; j++) dv[j] = dp[(size_t)(r0 + j) * 128];
#pragma unroll
                for (int j = 0; j < 8; j++) s = fmaf(g2[r0 + j], dv[j], s);
            }
            g_c0p[i * 128 + t] = s;
        }
        return;
    }

    extern __shared__ float ps[];
    float* sD1  = ps;           // [128 hp][128 h]
    float* sG2T = ps + 16384;   // [128 hp][36]

    const int i  = bx >> 2;
    const int k0 = (bx & 3) * 32;

    for (int idx = t; idx < 16384; idx += 256)
        sD1[idx] = D1[(size_t)i * 16384 + idx];
    for (int idx = t; idx < 4096; idx += 256) {
        int kk = idx & 31, hp = idx >> 5;
        sG2T[hp * 36 + kk] = G2[(size_t)(k0 + kk) * 128 + hp];
    }
    __syncthreads();

    const int h  = t & 127;
    const int kb = (t >> 7) * 16;
    float acc[16];
#pragma unroll
    for (int kk = 0; kk < 16; kk++) acc[kk] = 0.f;

    for (int hp = 0; hp < 128; hp++) {
        float dv = sD1[hp * 128 + h];
        const float* gp = &sG2T[hp * 36 + kb];
        float4 ga = *(const float4*)(gp);
        float4 gb = *(const float4*)(gp + 4);
        float4 gc = *(const float4*)(gp + 8);
        float4 gd = *(const float4*)(gp + 12);
        acc[0]  = fmaf(ga.x, dv, acc[0]);  acc[1]  = fmaf(ga.y, dv, acc[1]);
        acc[2]  = fmaf(ga.z, dv, acc[2]);  acc[3]  = fmaf(ga.w, dv, acc[3]);
        acc[4]  = fmaf(gb.x, dv, acc[4]);  acc[5]  = fmaf(gb.y, dv, acc[5]);
        acc[6]  = fmaf(gb.z, dv, acc[6]);  acc[7]  = fmaf(gb.w, dv, acc[7]);
        acc[8]  = fmaf(gc.x, dv, acc[8]);  acc[9]  = fmaf(gc.y, dv, acc[9]);
        acc[10] = fmaf(gc.z, dv, acc[10]); acc[11] = fmaf(gc.w, dv, acc[11]);
        acc[12] = fmaf(gd.x, dv, acc[12]); acc[13] = fmaf(gd.y, dv, acc[13]);
        acc[14] = fmaf(gd.z, dv, acc[14]); acc[15] = fmaf(gd.w, dv, acc[15]);
    }
#pragma unroll
    for (int kk = 0; kk < 16; kk++)
        g_E[(size_t)(i * 128 + k0 + kb + kk) * 128 + h] = f2tf32(acc[kk]);
}

// ---------------------------------------------------------------------------
// dec: out[b] = relu(Y[b] @ E + c0) . D2 + d2, tf32 mma. (round-4, known-good)
// ---------------------------------------------------------------------------
#define AS_STRIDE 36
#define BS_STRIDE 136

__global__ void __launch_bounds__(256) dec_kernel(
    const float* __restrict__ d1, const float* __restrict__ D2,
    const float* __restrict__ d2, float* __restrict__ out)
{
    __shared__ __align__(16) uint32_t As[64 * AS_STRIDE];
    __shared__ __align__(16) uint32_t Bs[32 * BS_STRIDE];
    __shared__ float rowsum[4][64];

    const int t    = threadIdx.x;
    const int m0   = blockIdx.x * 64;
    const int wid  = t >> 5;
    const int lane = t & 31;
    const int wm   = wid >> 2;
    const int wn   = wid & 3;
    const int g    = lane >> 2;
    const int tg   = lane & 3;

    const int arow = t >> 2;
    const int akc  = (t & 3) * 8;
    const int bkk  = t >> 3;
    const int bn   = (t & 7) * 16;

    const uint32_t* Y = (const uint32_t*)(g_buf + UV_OFF);

    float c[2][4][4];
#pragma unroll
    for (int mf = 0; mf < 2; mf++)
#pragma unroll
        for (int nf = 0; nf < 4; nf++)
#pragma unroll
            for (int q = 0; q < 4; q++) c[mf][nf][q] = 0.f;

    for (int k0 = 0; k0 < KTOT; k0 += 32) {
        {
            const uint32_t* yp = Y +
                ((size_t)(k0 >> 7) * BATCH + (m0 + arow)) * 128 + (k0 & 127) + akc;
            uint4 a0 = *(const uint4*)yp;
            uint4 a1 = *(const uint4*)(yp + 4);
            *(uint4*)&As[arow * AS_STRIDE + akc]     = a0;
            *(uint4*)&As[arow * AS_STRIDE + akc + 4] = a1;
        }
        {
            const uint32_t* ep = g_E + (size_t)(k0 + bkk) * 128 + bn;
            uint4 e0 = *(const uint4*)ep;
            uint4 e1 = *(const uint4*)(ep + 4);
            uint4 e2 = *(const uint4*)(ep + 8);
            uint4 e3 = *(const uint4*)(ep + 12);
            *(uint4*)&Bs[bkk * BS_STRIDE + bn]      = e0;
            *(uint4*)&Bs[bkk * BS_STRIDE + bn + 4]  = e1;
            *(uint4*)&Bs[bkk * BS_STRIDE + bn + 8]  = e2;
            *(uint4*)&Bs[bkk * BS_STRIDE + bn + 12] = e3;
        }
        __syncthreads();

#pragma unroll
        for (int kk = 0; kk < 32; kk += 8) {
            uint32_t a[2][4], bfr[4][2];
#pragma unroll
            for (int mf = 0; mf < 2; mf++) {
                const uint32_t* ap = &As[(wm * 32 + mf * 16 + g) * AS_STRIDE + kk + tg];
                a[mf][0] = ap[0];
                a[mf][1] = ap[8 * AS_STRIDE];
                a[mf][2] = ap[4];
                a[mf][3] = ap[8 * AS_STRIDE + 4];
            }
#pragma unroll
            for (int nf = 0; nf < 4; nf++) {
                const uint32_t* bp = &Bs[(kk + tg) * BS_STRIDE + wn * 32 + nf * 8 + g];
                bfr[nf][0] = bp[0];
                bfr[nf][1] = bp[4 * BS_STRIDE];
            }
#pragma unroll
            for (int mf = 0; mf < 2; mf++)
#pragma unroll
                for (int nf = 0; nf < 4; nf++)
                    MMA_TF32(c[mf][nf], a[mf][0], a[mf][1], a[mf][2], a[mf][3],
                             bfr[nf][0], bfr[nf][1]);
        }
        __syncthreads();
    }

    float c0v[4][2], d2v[4][2];
#pragma unroll
    for (int nf = 0; nf < 4; nf++) {
#pragma unroll
        for (int j = 0; j < 2; j++) {
            int col = wn * 32 + nf * 8 + tg * 2 + j;
            float base = d1[col];
#pragma unroll
            for (int ii = 0; ii < NCLS; ii++) base += g_c0p[ii * 128 + col];
            c0v[nf][j] = base;
            d2v[nf][j] = D2[col];
        }
    }

#pragma unroll
    for (int mf = 0; mf < 2; mf++) {
        float p0 = 0.f, p1 = 0.f;
#pragma unroll
        for (int nf = 0; nf < 4; nf++) {
            p0 = fmaf(fmaxf(c[mf][nf][0] + c0v[nf][0], 0.f), d2v[nf][0], p0);
            p0 = fmaf(fmaxf(c[mf][nf][1] + c0v[nf][1], 0.f), d2v[nf][1], p0);
            p1 = fmaf(fmaxf(c[mf][nf][2] + c0v[nf][0], 0.f), d2v[nf][0], p1);
            p1 = fmaf(fmaxf(c[mf][nf][3] + c0v[nf][1], 0.f), d2v[nf][1], p1);
        }
        p0 += __shfl_xor_sync(0xffffffffu, p0, 1);
        p0 += __shfl_xor_sync(0xffffffffu, p0, 2);
        p1 += __shfl_xor_sync(0xffffffffu, p1, 1);
        p1 += __shfl_xor_sync(0xffffffffu, p1, 2);
        if (tg == 0) {
            rowsum[wn][wm * 32 + mf * 16 + g]     = p0;
            rowsum[wn][wm * 32 + mf * 16 + g + 8] = p1;
        }
    }
    __syncthreads();

    if (t < 64) {
        float s = rowsum[0][t] + rowsum[1][t] + rowsum[2][t] + rowsum[3][t];
        out[m0 + t] = s + d2[0];
    }
}

// ---------------------------------------------------------------------------
extern "C" void kernel_launch(void* const* d_in, const int* in_sizes, int n_in,
                              void* d_out, int out_size) {
    const float* hidden = (const float*)d_in[1];
    const float* W1 = (const float*)d_in[2];
    const float* b1 = (const float*)d_in[3];
    const float* W2 = (const float*)d_in[4];
    const float* b2 = (const float*)d_in[5];
    const float* G1 = (const float*)d_in[6];
    const float* g1 = (const float*)d_in[7];
    const float* G2 = (const float*)d_in[8];
    const float* g2 = (const float*)d_in[9];
    const float* D1 = (const float*)d_in[10];
    const float* d1 = (const float*)d_in[11];
    const float* D2 = (const float*)d_in[12];
    const float* d2 = (const float*)d_in[13];
    float* out = (float*)d_out;

    const int SMEM_UV = (128 * GA_STR + 64 * GB_STR + 128) * 4;  // 70144
    const int SMEM_Y  = (160 * GA_STR + 64 * GB_STR +
                         160 * ND_STR + 16 * ADJ_PAD + 128) * 4; // ~127.7KB
    const int SMEM_PREP = (16384 + 128 * 36) * 4;                // 83968

    cudaFuncSetAttribute(uv_gemm,     cudaFuncAttributeMaxDynamicSharedMemorySize, SMEM_UV);
    cudaFuncSetAttribute(y_gemm,      cudaFuncAttributeMaxDynamicSharedMemorySize, SMEM_Y);
    cudaFuncSetAttribute(prep_kernel, cudaFuncAttributeMaxDynamicSharedMemorySize, SMEM_PREP);

    uv_gemm<<<MTOT / 128, 256, SMEM_UV>>>(hidden, W1, b1);
    adj_kernel<<<BATCH / 8, 256>>>(W2, b2);
    y_gemm<<<BATCH / 16, 256, SMEM_Y>>>(hidden, G1, g1);
    prep_kernel<<<50, 256, SMEM_PREP>>>(G2, g2, D1);
    dec_kernel<<<BATCH / 64, 256>>>(d1, D2, d2, out);
}

// round 13
// speedup vs baseline: 1.0617x; 1.0617x over previous
#include <cuda_runtime.h>
#include <math.h>
#include <stdint.h>

#define BATCH 8192
#define NCLS  10
#define FEAT  64
#define HID   128
#define KTOT  (NCLS * HID)   // 1280
#define MTOT  (NCLS * BATCH) // 81920 rows, row = n*8192 + b

// ---------------------------------------------------------------------------
// Static scratch, ~43.8 MB (round-10 layout, known to pass the mem guard).
// g_buf phases:
//   [0, 10485760)            phase 1-2: UV f32 (u+b1 cols 0-63, v cols 64-127)
//                            phase 3-5: Y  tf32 bits (row = i*8192+b)
//   [10485760, 11304960)     phase 2-3: adj f32 [8192][100]
// ---------------------------------------------------------------------------
#define UV_OFF  0
#define ADJ_OFF 10485760
__device__ __align__(16) float    g_buf[11304960];
__device__ __align__(16) uint32_t g_E[NCLS * HID * HID];   // tf32 E[i][k][h]
__device__ __align__(16) float    g_c0p[NCLS * HID];       // f32 partial c0

__device__ __forceinline__ uint32_t f2tf32(float x) {
    uint32_t r;
    asm("cvt.rna.tf32.f32 %0, %1;" : "=r"(r) : "f"(x));
    return r;
}

#define MMA_TF32(C, A0, A1, A2, A3, B0, B1)                                  \
    asm volatile(                                                            \
        "mma.sync.aligned.m16n8k8.row.col.f32.tf32.tf32.f32 "               \
        "{%0,%1,%2,%3}, {%4,%5,%6,%7}, {%8,%9}, {%0,%1,%2,%3};"             \
        : "+f"((C)[0]), "+f"((C)[1]), "+f"((C)[2]), "+f"((C)[3])            \
        : "r"(A0), "r"(A1), "r"(A2), "r"(A3), "r"(B0), "r"(B1))

#define GA_STR 68    // 68 mod 32 = 4 -> A-frag banks 4g+tg distinct
#define GB_STR 136   // 136 mod 32 = 8 -> B-frag banks 8tg+g distinct

// ---------------------------------------------------------------------------
// prep body (round-10 prep math, as device function). pbx in [0,50).
// Uses 83968 B of dynamic smem.
// ---------------------------------------------------------------------------
__device__ void prep_body(int pbx, int t, float* ps,
                          const float* __restrict__ G2,
                          const float* __restrict__ g2,
                          const float* __restrict__ D1)
{
    if (pbx >= 40) {
        const int i = pbx - 40;
        if (t < 128) {
            const float* dp = D1 + (size_t)(i * 128) * 128 + t;
            float s = 0.f;
            for (int r0 = 0; r0 < 128; r0 += 8) {
                float dv[8];
#pragma unroll
                for (int j = 0; j < 8; j++) dv[j] = dp[(size_t)(r0 + j) * 128];
#pragma unroll
                for (int j = 0; j < 8; j++) s = fmaf(g2[r0 + j], dv[j], s);
            }
            g_c0p[i * 128 + t] = s;
        }
        return;
    }

    float* sD1  = ps;           // [128 hp][128 h]
    float* sG2T = ps + 16384;   // [128 hp][36]

    const int i  = pbx >> 2;
    const int k0 = (pbx & 3) * 32;

    for (int idx = t; idx < 16384; idx += 256)
        sD1[idx] = D1[(size_t)i * 16384 + idx];
    for (int idx = t; idx < 4096; idx += 256) {
        int kk = idx & 31, hp = idx >> 5;
        sG2T[hp * 36 + kk] = G2[(size_t)(k0 + kk) * 128 + hp];
    }
    __syncthreads();

    const int h  = t & 127;
    const int kb = (t >> 7) * 16;
    float acc[16];
#pragma unroll
    for (int kk = 0; kk < 16; kk++) acc[kk] = 0.f;

    for (int hp = 0; hp < 128; hp++) {
        float dv = sD1[hp * 128 + h];
        const float* gp = &sG2T[hp * 36 + kb];
        float4 ga = *(const float4*)(gp);
        float4 gb = *(const float4*)(gp + 4);
        float4 gc = *(const float4*)(gp + 8);
        float4 gd = *(const float4*)(gp + 12);
        acc[0]  = fmaf(ga.x, dv, acc[0]);  acc[1]  = fmaf(ga.y, dv, acc[1]);
        acc[2]  = fmaf(ga.z, dv, acc[2]);  acc[3]  = fmaf(ga.w, dv, acc[3]);
        acc[4]  = fmaf(gb.x, dv, acc[4]);  acc[5]  = fmaf(gb.y, dv, acc[5]);
        acc[6]  = fmaf(gb.z, dv, acc[6]);  acc[7]  = fmaf(gb.w, dv, acc[7]);
        acc[8]  = fmaf(gc.x, dv, acc[8]);  acc[9]  = fmaf(gc.y, dv, acc[9]);
        acc[10] = fmaf(gc.z, dv, acc[10]); acc[11] = fmaf(gc.w, dv, acc[11]);
        acc[12] = fmaf(gd.x, dv, acc[12]); acc[13] = fmaf(gd.y, dv, acc[13]);
        acc[14] = fmaf(gd.z, dv, acc[14]); acc[15] = fmaf(gd.w, dv, acc[15]);
    }
#pragma unroll
    for (int kk = 0; kk < 16; kk++)
        g_E[(size_t)(i * 128 + k0 + kb + kk) * 128 + h] = f2tf32(acc[kk]);
}

// ---------------------------------------------------------------------------
// Kernel 1: blocks [0,640) = UV GEMM (round-10 uv_gemm, unchanged math);
//           blocks [640,690) = prep (overlapped on the same launch).
// 256 threads. UV: block tile 128x128, warp tile 64x32.
// ---------------------------------------------------------------------------
__global__ void __launch_bounds__(256) uvprep_kernel(
    const float* __restrict__ A, const float* __restrict__ W1,
    const float* __restrict__ b1,
    const float* __restrict__ G2, const float* __restrict__ g2,
    const float* __restrict__ D1)
{
    extern __shared__ uint32_t gs[];
    const int t = threadIdx.x;

    if (blockIdx.x >= 640) {
        prep_body(blockIdx.x - 640, t, (float*)gs, G2, g2, D1);
        return;
    }

    uint32_t* sA = gs;                 // [128][GA_STR]
    uint32_t* sB = gs + 128 * GA_STR;  // [64][GB_STR]
    float* sbias = (float*)(sB + 64 * GB_STR);

    const int m0 = blockIdx.x * 128;

    {
        const float4* ap = (const float4*)(A + (size_t)m0 * 64);
        for (int idx = t; idx < 2048; idx += 256) {
            float4 v = ap[idx];
            int row = idx >> 4, c4 = (idx & 15) * 4;
            uint32_t* d = &sA[row * GA_STR + c4];
            d[0] = f2tf32(v.x); d[1] = f2tf32(v.y);
            d[2] = f2tf32(v.z); d[3] = f2tf32(v.w);
        }
    }
    for (int idx = t; idx < 8192; idx += 256) {
        int k = idx >> 7, c = idx & 127;
        float f = (c < 64) ? W1[k * 64 + c] : W1[(64 + k) * 64 + (c - 64)];
        sB[k * GB_STR + c] = f2tf32(f);
    }
    if (t < 64) sbias[t] = b1[t];
    __syncthreads();

    const int wid  = t >> 5;
    const int lane = t & 31;
    const int g    = lane >> 2;
    const int tg   = lane & 3;
    const int wm   = wid >> 2;
    const int wn   = wid & 3;

    float c[4][4][4];
#pragma unroll
    for (int mf = 0; mf < 4; mf++)
#pragma unroll
        for (int nf = 0; nf < 4; nf++)
#pragma unroll
            for (int q = 0; q < 4; q++) c[mf][nf][q] = 0.f;

#pragma unroll
    for (int kk = 0; kk < 8; kk++) {
        uint32_t a[4][4], bf[4][2];
#pragma unroll
        for (int mf = 0; mf < 4; mf++) {
            const uint32_t* ap = &sA[(wm * 64 + mf * 16 + g) * GA_STR + kk * 8 + tg];
            a[mf][0] = ap[0];
            a[mf][1] = ap[8 * GA_STR];
            a[mf][2] = ap[4];
            a[mf][3] = ap[8 * GA_STR + 4];
        }
#pragma unroll
        for (int nf = 0; nf < 4; nf++) {
            const uint32_t* bp = &sB[(kk * 8 + tg) * GB_STR + wn * 32 + nf * 8 + g];
            bf[nf][0] = bp[0];
            bf[nf][1] = bp[4 * GB_STR];
        }
#pragma unroll
        for (int mf = 0; mf < 4; mf++)
#pragma unroll
            for (int nf = 0; nf < 4; nf++)
                MMA_TF32(c[mf][nf], a[mf][0], a[mf][1], a[mf][2], a[mf][3],
                         bf[nf][0], bf[nf][1]);
    }

    float* UV = g_buf + UV_OFF;
#pragma unroll
    for (int mf = 0; mf < 4; mf++) {
#pragma unroll
        for (int nf = 0; nf < 4; nf++) {
            const int row = m0 + wm * 64 + mf * 16 + g;
            const int col = wn * 32 + nf * 8 + 2 * tg;
            float b0 = (col < 64) ? sbias[col] : 0.f;
            float b1v = (col < 64) ? sbias[col + 1] : 0.f;
            *(float2*)&UV[(size_t)row * 128 + col] =
                make_float2(c[mf][nf][0] + b0, c[mf][nf][1] + b1v);
            *(float2*)&UV[(size_t)(row + 8) * 128 + col] =
                make_float2(c[mf][nf][2] + b0, c[mf][nf][3] + b1v);
        }
    }
}

// ---------------------------------------------------------------------------
// Kernel 2: adjacency only. One warp per batch, 8 warps/block, grid 1024.
// (round-10 version, passed; wb 16B-aligned, sb2 padded)
// ---------------------------------------------------------------------------
#define AJ_STR 68

__global__ void __launch_bounds__(256) adj_kernel(
    const float* __restrict__ W2, const float* __restrict__ b2)
{
    __shared__ __align__(16) float wb[8 * 2 * 10 * AJ_STR];  // su/sv per warp
    __shared__ __align__(16) float sW2[64];
    __shared__ float sb2[4];

    const int t = threadIdx.x;
    if (t < 64) sW2[t] = W2[t];
    if (t == 64) sb2[0] = b2[0];
    __syncthreads();

    const int wid  = t >> 5;
    const int lane = t & 31;
    const int b    = blockIdx.x * 8 + wid;

    float* su = wb + wid * (2 * 10 * AJ_STR);
    float* sv = su + 10 * AJ_STR;

    const float* UV = g_buf + UV_OFF;
    {
        const int c4 = 4 * lane;
#pragma unroll
        for (int n = 0; n < NCLS; n++) {
            float4 v = *(const float4*)&UV[((size_t)(n * BATCH + b)) * 128 + c4];
            if (c4 < 64) *(float4*)&su[n * AJ_STR + c4] = v;
            else         *(float4*)&sv[n * AJ_STR + c4 - 64] = v;
        }
    }
    __syncwarp();

    float* adj = g_buf + ADJ_OFF + (size_t)b * 100;
    const float b2v = sb2[0];
    for (int p = lane; p < 100; p += 32) {
        int i = p / 10, j = p - i * 10;
        float s = b2v;
#pragma unroll 4
        for (int q = 0; q < 16; q++) {
            float4 u4 = *(const float4*)&su[i * AJ_STR + 4 * q];
            float4 v4 = *(const float4*)&sv[j * AJ_STR + 4 * q];
            float4 w4 = *(const float4*)&sW2[4 * q];
            s = fmaf(fmaxf(u4.x + v4.x, 0.f), w4.x, s);
            s = fmaf(fmaxf(u4.y + v4.y, 0.f), w4.y, s);
            s = fmaf(fmaxf(u4.z + v4.z, 0.f), w4.z, s);
            s = fmaf(fmaxf(u4.w + v4.w, 0.f), w4.w, s);
        }
        adj[p] = (i == j) ? 1.0f : (1.0f / (1.0f + __expf(-s)));
    }
}

// ---------------------------------------------------------------------------
// Kernel 3: y_gemm. Block = 16 batches x 10 nodes = 160 rows. grid 512.
// (round-10 version, passed)
// ---------------------------------------------------------------------------
#define ND_STR 66
#define ADJ_PAD 104

__global__ void __launch_bounds__(256) y_gemm(
    const float* __restrict__ hidden,
    const float* __restrict__ G1, const float* __restrict__ g1)
{
    extern __shared__ uint32_t ys[];
    uint32_t* sA  = ys;                          // [160][GA_STR] tf32 X
    uint32_t* sB  = ys + 160 * GA_STR;           // [64][GB_STR] tf32 G1
    float* snd    = (float*)(sB + 64 * GB_STR);  // [10*16][ND_STR]
    float* sadj   = snd + 160 * ND_STR;          // [16][ADJ_PAD]
    float* sbias  = sadj + 16 * ADJ_PAD;         // [128]

    const int t  = threadIdx.x;
    const int b0 = blockIdx.x * 16;

    for (int idx = t; idx < 10240; idx += 256) {
        int n = idx >> 10, rem = idx & 1023;
        int bl = rem >> 6, f = rem & 63;
        snd[(n * 16 + bl) * ND_STR + f] =
            hidden[((size_t)n * BATCH + b0 + bl) * 64 + f];
    }
    {
        const float* ap = g_buf + ADJ_OFF + (size_t)b0 * 100;
        for (int idx = t; idx < 1600; idx += 256) {
            int bl = idx / 100, p = idx - bl * 100;
            sadj[bl * ADJ_PAD + p] = ap[bl * 100 + p];
        }
    }
    for (int idx = t; idx < 8192; idx += 256) {
        int k = idx >> 7, c = idx & 127;
        sB[k * GB_STR + c] = f2tf32(G1[idx]);
    }
    if (t < 128) sbias[t] = g1[t];
    __syncthreads();

    for (int idx = t; idx < 10240; idx += 256) {
        int r = idx >> 6, f = idx & 63;
        int i = r >> 4, bl = r & 15;
        float x = snd[r * ND_STR + f];
        const float* arow = &sadj[bl * ADJ_PAD + i * 10];
#pragma unroll
        for (int j = 0; j < NCLS; j++)
            x = fmaf(arow[j], snd[(j * 16 + bl) * ND_STR + f], x);
        sA[r * GA_STR + f] = f2tf32(x);
    }
    __syncthreads();

    const int wid  = t >> 5;
    const int lane = t & 31;
    const int g    = lane >> 2;
    const int tg   = lane & 3;
    const int wm   = wid >> 2;    // 0..1 -> rows wm*80
    const int wn   = wid & 3;     // 0..3 -> cols wn*32

    float c[5][4][4];
#pragma unroll
    for (int mf = 0; mf < 5; mf++)
#pragma unroll
        for (int nf = 0; nf < 4; nf++)
#pragma unroll
            for (int q = 0; q < 4; q++) c[mf][nf][q] = 0.f;

#pragma unroll
    for (int kk = 0; kk < 8; kk++) {
        uint32_t a[5][4], bf[4][2];
#pragma unroll
        for (int mf = 0; mf < 5; mf++) {
            const uint32_t* ap = &sA[(wm * 80 + mf * 16 + g) * GA_STR + kk * 8 + tg];
            a[mf][0] = ap[0];
            a[mf][1] = ap[8 * GA_STR];
            a[mf][2] = ap[4];
            a[mf][3] = ap[8 * GA_STR + 4];
        }
#pragma unroll
        for (int nf = 0; nf < 4; nf++) {
            const uint32_t* bp = &sB[(kk * 8 + tg) * GB_STR + wn * 32 + nf * 8 + g];
            bf[nf][0] = bp[0];
            bf[nf][1] = bp[4 * GB_STR];
        }
#pragma unroll
        for (int mf = 0; mf < 5; mf++)
#pragma unroll
            for (int nf = 0; nf < 4; nf++)
                MMA_TF32(c[mf][nf], a[mf][0], a[mf][1], a[mf][2], a[mf][3],
                         bf[nf][0], bf[nf][1]);
    }

    uint32_t* Y = (uint32_t*)(g_buf + UV_OFF);
#pragma unroll
    for (int mf = 0; mf < 5; mf++) {
#pragma unroll
        for (int nf = 0; nf < 4; nf++) {
            const int col = wn * 32 + nf * 8 + 2 * tg;
            const float gg0 = sbias[col], gg1 = sbias[col + 1];
#pragma unroll
            for (int h = 0; h < 2; h++) {
                const int r = wm * 80 + mf * 16 + g + h * 8;
                const int i = r >> 4, bl = r & 15;
                const size_t grow = (size_t)i * BATCH + b0 + bl;
                uint2 o;
                o.x = f2tf32(fmaxf(c[mf][nf][0 + 2 * h] + gg0, 0.f));
                o.y = f2tf32(fmaxf(c[mf][nf][1 + 2 * h] + gg1, 0.f));
                *(uint2*)&Y[grow * 128 + col] = o;
            }
        }
    }
}

// ---------------------------------------------------------------------------
// dec: out[b] = relu(Y[b] @ E + c0) . D2 + d2, tf32 mma. (known-good)
// ---------------------------------------------------------------------------
#define AS_STRIDE 36
#define BS_STRIDE 136

__global__ void __launch_bounds__(256) dec_kernel(
    const float* __restrict__ d1, const float* __restrict__ D2,
    const float* __restrict__ d2, float* __restrict__ out)
{
    __shared__ __align__(16) uint32_t As[64 * AS_STRIDE];
    __shared__ __align__(16) uint32_t Bs[32 * BS_STRIDE];
    __shared__ float rowsum[4][64];

    const int t    = threadIdx.x;
    const int m0   = blockIdx.x * 64;
    const int wid  = t >> 5;
    const int lane = t & 31;
    const int wm   = wid >> 2;
    const int wn   = wid & 3;
    const int g    = lane >> 2;
    const int tg   = lane & 3;

    const int arow = t >> 2;
    const int akc  = (t & 3) * 8;
    const int bkk  = t >> 3;
    const int bn   = (t & 7) * 16;

    const uint32_t* Y = (const uint32_t*)(g_buf + UV_OFF);

    float c[2][4][4];
#pragma unroll
    for (int mf = 0; mf < 2; mf++)
#pragma unroll
        for (int nf = 0; nf < 4; nf++)
#pragma unroll
            for (int q = 0; q < 4; q++) c[mf][nf][q] = 0.f;

    for (int k0 = 0; k0 < KTOT; k0 += 32) {
        {
            const uint32_t* yp = Y +
                ((size_t)(k0 >> 7) * BATCH + (m0 + arow)) * 128 + (k0 & 127) + akc;
            uint4 a0 = *(const uint4*)yp;
            uint4 a1 = *(const uint4*)(yp + 4);
            *(uint4*)&As[arow * AS_STRIDE + akc]     = a0;
            *(uint4*)&As[arow * AS_STRIDE + akc + 4] = a1;
        }
        {
            const uint32_t* ep = g_E + (size_t)(k0 + bkk) * 128 + bn;
            uint4 e0 = *(const uint4*)ep;
            uint4 e1 = *(const uint4*)(ep + 4);
            uint4 e2 = *(const uint4*)(ep + 8);
            uint4 e3 = *(const uint4*)(ep + 12);
            *(uint4*)&Bs[bkk * BS_STRIDE + bn]      = e0;
            *(uint4*)&Bs[bkk * BS_STRIDE + bn + 4]  = e1;
            *(uint4*)&Bs[bkk * BS_STRIDE + bn + 8]  = e2;
            *(uint4*)&Bs[bkk * BS_STRIDE + bn + 12] = e3;
        }
        __syncthreads();

#pragma unroll
        for (int kk = 0; kk < 32; kk += 8) {
            uint32_t a[2][4], bfr[4][2];
#pragma unroll
            for (int mf = 0; mf < 2; mf++) {
                const uint32_t* ap = &As[(wm * 32 + mf * 16 + g) * AS_STRIDE + kk + tg];
                a[mf][0] = ap[0];
                a[mf][1] = ap[8 * AS_STRIDE];
                a[mf][2] = ap[4];
                a[mf][3] = ap[8 * AS_STRIDE + 4];
            }
#pragma unroll
            for (int nf = 0; nf < 4; nf++) {
                const uint32_t* bp = &Bs[(kk + tg) * BS_STRIDE + wn * 32 + nf * 8 + g];
                bfr[nf][0] = bp[0];
                bfr[nf][1] = bp[4 * BS_STRIDE];
            }
#pragma unroll
            for (int mf = 0; mf < 2; mf++)
#pragma unroll
                for (int nf = 0; nf < 4; nf++)
                    MMA_TF32(c[mf][nf], a[mf][0], a[mf][1], a[mf][2], a[mf][3],
                             bfr[nf][0], bfr[nf][1]);
        }
        __syncthreads();
    }

    float c0v[4][2], d2v[4][2];
#pragma unroll
    for (int nf = 0; nf < 4; nf++) {
#pragma unroll
        for (int j = 0; j < 2; j++) {
            int col = wn * 32 + nf * 8 + tg * 2 + j;
            float base = d1[col];
#pragma unroll
            for (int ii = 0; ii < NCLS; ii++) base += g_c0p[ii * 128 + col];
            c0v[nf][j] = base;
            d2v[nf][j] = D2[col];
        }
    }

#pragma unroll
    for (int mf = 0; mf < 2; mf++) {
        float p0 = 0.f, p1 = 0.f;
#pragma unroll
        for (int nf = 0; nf < 4; nf++) {
            p0 = fmaf(fmaxf(c[mf][nf][0] + c0v[nf][0], 0.f), d2v[nf][0], p0);
            p0 = fmaf(fmaxf(c[mf][nf][1] + c0v[nf][1], 0.f), d2v[nf][1], p0);
            p1 = fmaf(fmaxf(c[mf][nf][2] + c0v[nf][0], 0.f), d2v[nf][0], p1);
            p1 = fmaf(fmaxf(c[mf][nf][3] + c0v[nf][1], 0.f), d2v[nf][1], p1);
        }
        p0 += __shfl_xor_sync(0xffffffffu, p0, 1);
        p0 += __shfl_xor_sync(0xffffffffu, p0, 2);
        p1 += __shfl_xor_sync(0xffffffffu, p1, 1);
        p1 += __shfl_xor_sync(0xffffffffu, p1, 2);
        if (tg == 0) {
            rowsum[wn][wm * 32 + mf * 16 + g]     = p0;
            rowsum[wn][wm * 32 + mf * 16 + g + 8] = p1;
        }
    }
    __syncthreads();

    if (t < 64) {
        float s = rowsum[0][t] + rowsum[1][t] + rowsum[2][t] + rowsum[3][t];
        out[m0 + t] = s + d2[0];
    }
}

// ---------------------------------------------------------------------------
extern "C" void kernel_launch(void* const* d_in, const int* in_sizes, int n_in,
                              void* d_out, int out_size) {
    const float* hidden = (const float*)d_in[1];
    const float* W1 = (const float*)d_in[2];
    const float* b1 = (const float*)d_in[3];
    const float* W2 = (const float*)d_in[4];
    const float* b2 = (const float*)d_in[5];
    const float* G1 = (const float*)d_in[6];
    const float* g1 = (const float*)d_in[7];
    const float* G2 = (const float*)d_in[8];
    const float* g2 = (const float*)d_in[9];
    const float* D1 = (const float*)d_in[10];
    const float* d1 = (const float*)d_in[11];
    const float* D2 = (const float*)d_in[12];
    const float* d2 = (const float*)d_in[13];
    float* out = (float*)d_out;

    const int SMEM_UVP = 83968;                 // max(uv 70144, prep 83968)
    const int SMEM_Y   = (160 * GA_STR + 64 * GB_STR +
                          160 * ND_STR + 16 * ADJ_PAD + 128) * 4;  // ~127.7KB

    cudaFuncSetAttribute(uvprep_kernel, cudaFuncAttributeMaxDynamicSharedMemorySize,
                         SMEM_UVP);
    cudaFuncSetAttribute(y_gemm, cudaFuncAttributeMaxDynamicSharedMemorySize,
                         SMEM_Y);

    uvprep_kernel<<<690, 256, SMEM_UVP>>>(hidden, W1, b1, G2, g2, D1);
    adj_kernel<<<BATCH / 8, 256>>>(W2, b2);
    y_gemm<<<BATCH / 16, 256, SMEM_Y>>>(hidden, G1, g1);
    dec_kernel<<<BATCH / 64, 256>>>(d1, D2, d2, out);
}